// round 8
// baseline (speedup 1.0000x reference)
#include <cuda_runtime.h>
#include <cuda_bf16.h>
#include <cuda_fp16.h>
#include <cstdint>
#include <math.h>

#define T_DIM 2048
#define B_DIM 4
#define E_DIM 512
#define H_DIM 8
#define HD    64
#define BH    (B_DIM*H_DIM)
#define SCALE 0.125f
#define M_ROWS (T_DIM*B_DIM)
#define ATTN_ELEMS (T_DIM*B_DIM*E_DIM)

// ---------------- scratch globals ----------------
__device__ __nv_bfloat16 g_xh[M_ROWS * E_DIM];
__device__ __nv_bfloat16 g_xl[M_ROWS * E_DIM];
__device__ __nv_bfloat16 g_wih[3 * E_DIM * E_DIM];
__device__ __nv_bfloat16 g_wil[3 * E_DIM * E_DIM];
__device__ __nv_bfloat16 g_woh[E_DIM * E_DIM];
__device__ __nv_bfloat16 g_wol[E_DIM * E_DIM];
__device__ __nv_bfloat16 g_qh[BH * T_DIM * HD];
__device__ __nv_bfloat16 g_ql[BH * T_DIM * HD];
__device__ __nv_bfloat16 g_kh[BH * T_DIM * HD];
__device__ __nv_bfloat16 g_kl[BH * T_DIM * HD];
__device__ __nv_bfloat16 g_vth[BH * HD * T_DIM];   // [bh][d][t]
__device__ __nv_bfloat16 g_vtl[BH * HD * T_DIM];
__device__ __nv_bfloat16 g_ch[M_ROWS * E_DIM];     // ctx hi  [t*B+b][e]
__device__ __nv_bfloat16 g_cl[M_ROWS * E_DIM];
__device__ float g_il[BH * T_DIM];
__device__ __align__(16) __half g_p[(size_t)BH * T_DIM * T_DIM];  // 256MB

// ---------------- helpers ----------------
__device__ __forceinline__ uint32_t smem_u32(const void* p) {
    uint32_t a;
    asm("{ .reg .u64 t; cvta.to.shared.u64 t, %1; cvt.u32.u64 %0, t; }" : "=r"(a) : "l"(p));
    return a;
}

__device__ __forceinline__ void ldsm4(uint32_t addr, uint32_t* r) {
    asm volatile("ldmatrix.sync.aligned.m8n8.x4.shared.b16 {%0,%1,%2,%3}, [%4];"
                 : "=r"(r[0]), "=r"(r[1]), "=r"(r[2]), "=r"(r[3]) : "r"(addr));
}

__device__ __forceinline__ void mma_bf(float* c, const uint32_t* a, const uint32_t* b) {
    asm volatile("mma.sync.aligned.m16n8k16.row.col.f32.bf16.bf16.f32 "
                 "{%0,%1,%2,%3},{%4,%5,%6,%7},{%8,%9},{%0,%1,%2,%3};"
                 : "+f"(c[0]), "+f"(c[1]), "+f"(c[2]), "+f"(c[3])
                 : "r"(a[0]), "r"(a[1]), "r"(a[2]), "r"(a[3]), "r"(b[0]), "r"(b[1]));
}

__device__ __forceinline__ void cpa16(uint32_t dst, const void* src) {
    asm volatile("cp.async.cg.shared.global [%0], [%1], 16;" :: "r"(dst), "l"(src));
}
#define CP_COMMIT() asm volatile("cp.async.commit_group;" ::: "memory")
#define CP_WAIT1()  asm volatile("cp.async.wait_group 1;" ::: "memory")

// tiles: rows x 64 bf16, row pitch 128B, 16B-chunk XOR swizzle
__device__ __forceinline__ uint32_t addrA(uint32_t base, int m0, int kc, int lane) {
    int g = lane >> 3, r8 = lane & 7;
    int row = m0 + r8 + ((g & 1) << 3);
    int ch  = kc + (g >> 1);
    return base + row * 128 + ((ch ^ (row & 7)) << 4);
}
__device__ __forceinline__ uint32_t addrB(uint32_t base, int n0, int kc, int lane) {
    int g = lane >> 3, r8 = lane & 7;
    int row = n0 + r8 + ((g >> 1) << 3);
    int ch  = kc + (g & 1);
    return base + row * 128 + ((ch ^ (row & 7)) << 4);
}

// 32x32 warp tile step for projection GEMMs (3 split passes)
__device__ __forceinline__ void warp_step(float c[2][4][4],
    uint32_t AHb, uint32_t ALb, uint32_t BHb, uint32_t BLb,
    int wm0, int wn0, int kc, int lane)
{
    uint32_t ah[2][4], al[2][4], bhf[4][2], blf[4][2];
    #pragma unroll
    for (int i = 0; i < 2; i++) {
        ldsm4(addrA(AHb, wm0 + i * 16, kc, lane), ah[i]);
        ldsm4(addrA(ALb, wm0 + i * 16, kc, lane), al[i]);
    }
    #pragma unroll
    for (int jj = 0; jj < 2; jj++) {
        uint32_t t[4];
        ldsm4(addrB(BHb, wn0 + jj * 16, kc, lane), t);
        bhf[jj*2][0] = t[0]; bhf[jj*2][1] = t[1];
        bhf[jj*2+1][0] = t[2]; bhf[jj*2+1][1] = t[3];
        ldsm4(addrB(BLb, wn0 + jj * 16, kc, lane), t);
        blf[jj*2][0] = t[0]; blf[jj*2][1] = t[1];
        blf[jj*2+1][0] = t[2]; blf[jj*2+1][1] = t[3];
    }
    #pragma unroll
    for (int i = 0; i < 2; i++)
        #pragma unroll
        for (int j = 0; j < 4; j++) {
            mma_bf(c[i][j], ah[i], bhf[j]);
            mma_bf(c[i][j], ah[i], blf[j]);
            mma_bf(c[i][j], al[i], bhf[j]);
        }
}

// fast hi/lo pack
__device__ __forceinline__ uint32_t packsplit2(float x, float y, uint32_t* lo) {
    __nv_bfloat162 h2 = __floats2bfloat162_rn(x, y);
    uint32_t hb = *(uint32_t*)&h2;
    float hx = __uint_as_float(hb << 16);
    float hy = __uint_as_float(hb & 0xffff0000u);
    __nv_bfloat162 l2 = __floats2bfloat162_rn(x - hx, y - hy);
    *lo = *(uint32_t*)&l2;
    return hb;
}

// ---------------- merged split kernel ----------------
#define NX  (M_ROWS * E_DIM)
#define NWI (3 * E_DIM * E_DIM)
#define NWO (E_DIM * E_DIM)
__global__ void split_all(const float* __restrict__ x,
                          const float* __restrict__ wi,
                          const float* __restrict__ wo)
{
    int i = blockIdx.x * blockDim.x + threadIdx.x;
    const float* src; __nv_bfloat16 *hi, *lo; int idx;
    if (i < NX)                { src = x;  hi = g_xh;  lo = g_xl;  idx = i; }
    else if (i < NX + NWI)     { src = wi; hi = g_wih; lo = g_wil; idx = i - NX; }
    else if (i < NX + NWI + NWO){ src = wo; hi = g_woh; lo = g_wol; idx = i - NX - NWI; }
    else return;
    float v = src[idx];
    __nv_bfloat16 h = __float2bfloat16(v);
    hi[idx] = h;
    lo[idx] = __float2bfloat16(v - __bfloat162float(h));
}

// ---------------- projection GEMM (cp.async double-buffered) ----------------
__device__ __forceinline__ void gemm_issue(uint32_t stage_base,
    const __nv_bfloat16* Ah, const __nv_bfloat16* Al,
    const __nv_bfloat16* Bh, const __nv_bfloat16* Bl,
    int m0, int n0, int ko, int tid)
{
    #pragma unroll
    for (int i = 0; i < 4; i++) {
        int idx = tid + i * 256;
        int r = idx >> 3, ch = idx & 7;
        uint32_t off = r * 128 + ((ch ^ (r & 7)) << 4);
        cpa16(stage_base + off,         Ah + (size_t)(m0 + r) * E_DIM + ko + ch * 8);
        cpa16(stage_base + 16384 + off, Al + (size_t)(m0 + r) * E_DIM + ko + ch * 8);
    }
    #pragma unroll
    for (int i = 0; i < 2; i++) {
        int idx = tid + i * 256;
        int r = idx >> 3, ch = idx & 7;
        uint32_t off = r * 128 + ((ch ^ (r & 7)) << 4);
        cpa16(stage_base + 32768 + off, Bh + (size_t)(n0 + r) * E_DIM + ko + ch * 8);
        cpa16(stage_base + 40960 + off, Bl + (size_t)(n0 + r) * E_DIM + ko + ch * 8);
    }
}

__global__ __launch_bounds__(256) void gemm_mma(const float* __restrict__ bias,
                                                float* __restrict__ C, int mode)
{
    extern __shared__ char smem[];
    const __nv_bfloat16 *Ah, *Al, *Bh, *Bl;
    if (mode == 0) { Ah = g_xh; Al = g_xl; Bh = g_wih; Bl = g_wil; }
    else           { Ah = g_ch; Al = g_cl; Bh = g_woh; Bl = g_wol; }

    const uint32_t sb = smem_u32(smem);
    const int tid = threadIdx.x, lane = tid & 31, wid = tid >> 5;
    const int wm0 = (wid & 3) * 32, wn0 = (wid >> 2) * 32;
    const int m0 = blockIdx.y * 128, n0 = blockIdx.x * 64;

    gemm_issue(sb,         Ah, Al, Bh, Bl, m0, n0, 0,  tid); CP_COMMIT();
    gemm_issue(sb + 49152, Ah, Al, Bh, Bl, m0, n0, 64, tid); CP_COMMIT();

    float c[2][4][4] = {};
    for (int s = 0; s < 8; s++) {
        CP_WAIT1();
        __syncthreads();
        uint32_t st = sb + (s & 1) * 49152;
        #pragma unroll
        for (int kc = 0; kc < 8; kc += 2)
            warp_step(c, st, st + 16384, st + 32768, st + 40960, wm0, wn0, kc, lane);
        __syncthreads();
        if (s + 2 < 8)
            gemm_issue(sb + (s & 1) * 49152, Ah, Al, Bh, Bl, m0, n0, (s + 2) * 64, tid);
        CP_COMMIT();
    }

    #pragma unroll
    for (int i = 0; i < 2; i++)
        #pragma unroll
        for (int j = 0; j < 4; j++)
            #pragma unroll
            for (int e = 0; e < 4; e++) {
                int rg = m0 + wm0 + i * 16 + (lane >> 2) + ((e >> 1) << 3);
                int n  = n0 + wn0 + j * 8 + (lane & 3) * 2 + (e & 1);
                float v = c[i][j][e] + bias[n];
                if (mode == 0) {
                    int t = rg >> 2, bb = rg & 3;
                    int sect = n >> 9, jm = n & 511;
                    int hh = jm >> 6, d = jm & 63;
                    int bh = bb * 8 + hh;
                    if (sect == 2) {
                        size_t dst = ((size_t)bh * HD + d) * T_DIM + t;
                        __nv_bfloat16 h = __float2bfloat16(v);
                        g_vth[dst] = h;
                        g_vtl[dst] = __float2bfloat16(v - __bfloat162float(h));
                    } else {
                        size_t dst = ((size_t)bh * T_DIM + t) * HD + d;
                        if (sect == 0) {
                            v *= SCALE;
                            __nv_bfloat16 h = __float2bfloat16(v);
                            g_qh[dst] = h;
                            g_ql[dst] = __float2bfloat16(v - __bfloat162float(h));
                        } else {
                            __nv_bfloat16 h = __float2bfloat16(v);
                            g_kh[dst] = h;
                            g_kl[dst] = __float2bfloat16(v - __bfloat162float(h));
                        }
                    }
                } else {
                    C[(size_t)rg * E_DIM + n] = v;
                }
            }
}

// ---------------- flash attention: phase-separated, 64KB smem (Q reused) ----------------
// 128 threads (4 warps), q-tile 128 (32 rows/warp, full k width per warp).
// smem: region A = [0, 32768) holds Q hi/lo during prologue, then KV stage 1.
//       region B = [32768, 65536) KV stage 0.
// KV stage internal: KH +0, KL +8192, VH +16384, VL +24576.
__device__ __forceinline__ void flash_issue_kv(uint32_t buf, int bh, int k0, int tid)
{
    #pragma unroll
    for (int i = 0; i < 4; i++) {
        int idx = tid + i * 128;
        int r = idx >> 3, ch = idx & 7;
        uint32_t off = r * 128 + ((ch ^ (r & 7)) << 4);
        const size_t kof = ((size_t)bh * T_DIM + k0 + r) * HD + ch * 8;
        const size_t vof = ((size_t)bh * HD + r) * T_DIM + k0 + ch * 8;
        cpa16(buf + off,         g_kh + kof);
        cpa16(buf + 8192 + off,  g_kl + kof);
        cpa16(buf + 16384 + off, g_vth + vof);
        cpa16(buf + 24576 + off, g_vtl + vof);
    }
}

__global__ __launch_bounds__(128, 3) void flash_mma()
{
    extern __shared__ char smem[];
    const uint32_t sb = smem_u32(smem);
    const int tid = threadIdx.x, lane = tid & 31, w = tid >> 5;
    const int bh = blockIdx.y, q0 = blockIdx.x * 128;
    const int b = bh >> 3, h = bh & 7;
    const int wq0 = w * 32;

    // prefetch KV tile0 -> region B
    flash_issue_kv(sb + 32768, bh, 0, tid);  CP_COMMIT();

    // load Q hi/lo into region A
    {
        const __nv_bfloat16* Qh = g_qh + ((size_t)bh * T_DIM + q0) * HD;
        const __nv_bfloat16* Ql = g_ql + ((size_t)bh * T_DIM + q0) * HD;
        #pragma unroll
        for (int i = 0; i < 8; i++) {
            int idx = tid + i * 128;
            int r = idx >> 3, ch = idx & 7;
            uint32_t off = r * 128 + ((ch ^ (r & 7)) << 4);
            *(uint4*)(smem + off)         = *(const uint4*)(Qh + (size_t)r * HD + ch * 8);
            *(uint4*)(smem + 16384 + off) = *(const uint4*)(Ql + (size_t)r * HD + ch * 8);
        }
    }
    __syncthreads();

    uint32_t qh[2][4][4], ql[2][4][4];
    #pragma unroll
    for (int i = 0; i < 2; i++)
        #pragma unroll
        for (int kk = 0; kk < 4; kk++) {
            ldsm4(addrA(sb,         wq0 + i * 16, 2 * kk, lane), qh[i][kk]);
            ldsm4(addrA(sb + 16384, wq0 + i * 16, 2 * kk, lane), ql[i][kk]);
        }
    __syncthreads();   // all warps done reading Q; region A is now free

    // prefetch KV tile1 -> region A
    flash_issue_kv(sb, bh, 64, tid); CP_COMMIT();

    float o[2][8][4] = {};
    float rs[4] = {};

    for (int kt = 0; kt < T_DIM / 64; kt++) {
        CP_WAIT1();
        __syncthreads();
        const uint32_t buf = (kt & 1) ? sb : sb + 32768;

        // S = Q K^T  (32 x 64 per warp)
        float s[2][8][4] = {};
        #pragma unroll
        for (int kk = 0; kk < 4; kk++)
            #pragma unroll
            for (int jj = 0; jj < 4; jj++) {
                uint32_t th[4], tl[4];
                ldsm4(addrB(buf,        jj * 16, 2 * kk, lane), th);
                ldsm4(addrB(buf + 8192, jj * 16, 2 * kk, lane), tl);
                uint32_t bh0[2] = {th[0], th[1]}, bh1[2] = {th[2], th[3]};
                uint32_t bl0[2] = {tl[0], tl[1]}, bl1[2] = {tl[2], tl[3]};
                #pragma unroll
                for (int i = 0; i < 2; i++) {
                    mma_bf(s[i][jj*2], qh[i][kk], bh0);
                    mma_bf(s[i][jj*2], qh[i][kk], bl0);
                    mma_bf(s[i][jj*2], ql[i][kk], bh0);
                    mma_bf(s[i][jj*2+1], qh[i][kk], bh1);
                    mma_bf(s[i][jj*2+1], qh[i][kk], bl1);
                    mma_bf(s[i][jj*2+1], ql[i][kk], bh1);
                }
            }

        // exp (MUFU) + row sums + stream P to gmem
        #pragma unroll
        for (int i = 0; i < 2; i++)
            #pragma unroll
            for (int j = 0; j < 8; j++) {
                float p0 = __expf(s[i][j][0]), p1 = __expf(s[i][j][1]);
                float p2 = __expf(s[i][j][2]), p3 = __expf(s[i][j][3]);
                s[i][j][0] = p0; s[i][j][1] = p1; s[i][j][2] = p2; s[i][j][3] = p3;
                rs[i*2]   += p0 + p1;
                rs[i*2+1] += p2 + p3;
                int col = kt * 64 + j * 8 + (lane & 3) * 2;
                int r0 = q0 + wq0 + i * 16 + (lane >> 2);
                __stcs((__half2*)(g_p + ((size_t)bh * T_DIM + r0) * T_DIM + col),
                       __floats2half2_rn(p0, p1));
                __stcs((__half2*)(g_p + ((size_t)bh * T_DIM + r0 + 8) * T_DIM + col),
                       __floats2half2_rn(p2, p3));
            }

        // pack P into PV A-fragments (registers only)
        uint32_t aPh[2][4][4], aPl[2][4][4];
        #pragma unroll
        for (int i = 0; i < 2; i++)
            #pragma unroll
            for (int kk = 0; kk < 4; kk++) {
                aPh[i][kk][0] = packsplit2(s[i][2*kk][0],   s[i][2*kk][1],   &aPl[i][kk][0]);
                aPh[i][kk][1] = packsplit2(s[i][2*kk][2],   s[i][2*kk][3],   &aPl[i][kk][1]);
                aPh[i][kk][2] = packsplit2(s[i][2*kk+1][0], s[i][2*kk+1][1], &aPl[i][kk][2]);
                aPh[i][kk][3] = packsplit2(s[i][2*kk+1][2], s[i][2*kk+1][3], &aPl[i][kk][3]);
            }

        // O += P V  (B = Vt in smem)
        #pragma unroll
        for (int kk = 0; kk < 4; kk++)
            #pragma unroll
            for (int jj = 0; jj < 4; jj++) {
                uint32_t th[4], tl[4];
                ldsm4(addrB(buf + 16384, jj * 16, 2 * kk, lane), th);
                ldsm4(addrB(buf + 24576, jj * 16, 2 * kk, lane), tl);
                uint32_t bh0[2] = {th[0], th[1]}, bh1[2] = {th[2], th[3]};
                uint32_t bl0[2] = {tl[0], tl[1]}, bl1[2] = {tl[2], tl[3]};
                #pragma unroll
                for (int i = 0; i < 2; i++) {
                    mma_bf(o[i][jj*2], aPh[i][kk], bh0);
                    mma_bf(o[i][jj*2], aPh[i][kk], bl0);
                    mma_bf(o[i][jj*2], aPl[i][kk], bh0);
                    mma_bf(o[i][jj*2+1], aPh[i][kk], bh1);
                    mma_bf(o[i][jj*2+1], aPh[i][kk], bl1);
                    mma_bf(o[i][jj*2+1], aPl[i][kk], bh1);
                }
            }
        __syncthreads();
        if (kt + 2 < T_DIM / 64)
            flash_issue_kv((kt & 1) ? sb : sb + 32768, bh, (kt + 2) * 64, tid);
        CP_COMMIT();
    }

    #pragma unroll
    for (int x = 0; x < 4; x++) {
        rs[x] += __shfl_xor_sync(0xffffffffu, rs[x], 1);
        rs[x] += __shfl_xor_sync(0xffffffffu, rs[x], 2);
    }
    float il[4] = {1.0f / rs[0], 1.0f / rs[1], 1.0f / rs[2], 1.0f / rs[3]};

    #pragma unroll
    for (int i = 0; i < 2; i++)
        #pragma unroll
        for (int hf = 0; hf < 2; hf++) {
            int r = wq0 + i * 16 + (lane >> 2) + hf * 8;
            float s_il = il[i*2 + hf];
            #pragma unroll
            for (int j = 0; j < 8; j++) {
                int cc = j * 8 + (lane & 3) * 2;
                uint32_t lo;
                uint32_t hi = packsplit2(o[i][j][hf*2] * s_il, o[i][j][hf*2+1] * s_il, &lo);
                size_t off = ((size_t)(q0 + r) * B_DIM + b) * E_DIM + h * HD + cc;
                *(uint32_t*)&g_ch[off] = hi;
                *(uint32_t*)&g_cl[off] = lo;
            }
            if ((lane & 3) == 0)
                g_il[(size_t)bh * T_DIM + q0 + r] = s_il;
        }
}

// ---------------- avg_weights: pure memory pass over stored P ----------------
__global__ __launch_bounds__(256) void avg_sum(float* __restrict__ outAvg)
{
    const int blk = blockIdx.x;
    const int b = blk >> 11, q = blk & 2047;
    const int tid = threadIdx.x;

    float acc[8] = {};
    #pragma unroll
    for (int hh = 0; hh < H_DIM; hh++) {
        const int bh = b * 8 + hh;
        float il = g_il[(size_t)bh * T_DIM + q] * 0.125f;
        uint4 u = *((const uint4*)(g_p + ((size_t)bh * T_DIM + q) * T_DIM) + tid);
        __half2* hp = (__half2*)&u;
        #pragma unroll
        for (int c = 0; c < 4; c++) {
            float2 f = __half22float2(hp[c]);
            acc[c*2]   = fmaf(f.x, il, acc[c*2]);
            acc[c*2+1] = fmaf(f.y, il, acc[c*2+1]);
        }
    }
    float* dst = outAvg + ((size_t)b * T_DIM + q) * T_DIM + tid * 8;
    *(float4*)dst       = make_float4(acc[0], acc[1], acc[2], acc[3]);
    *(float4*)(dst + 4) = make_float4(acc[4], acc[5], acc[6], acc[7]);
}

// ---------------- launch ----------------
extern "C" void kernel_launch(void* const* d_in, const int* in_sizes, int n_in,
                              void* d_out, int out_size)
{
    const float* x     = (const float*)d_in[0];
    const float* w_in  = (const float*)d_in[1];
    const float* b_in  = (const float*)d_in[2];
    const float* w_out = (const float*)d_in[3];
    const float* b_out = (const float*)d_in[4];
    float* out = (float*)d_out;

    static cudaStream_t s2 = nullptr;
    static cudaEvent_t ev1 = nullptr, ev2 = nullptr;
    if (!s2) {
        cudaStreamCreateWithFlags(&s2, cudaStreamNonBlocking);
        cudaEventCreateWithFlags(&ev1, cudaEventDisableTiming);
        cudaEventCreateWithFlags(&ev2, cudaEventDisableTiming);
    }

    split_all<<<(NX + NWI + NWO + 255) / 256, 256>>>(x, w_in, w_out);

    cudaFuncSetAttribute(gemm_mma, cudaFuncAttributeMaxDynamicSharedMemorySize, 98304);
    gemm_mma<<<dim3(3 * E_DIM / 64, M_ROWS / 128), 256, 98304>>>(b_in, out, 0);

    cudaFuncSetAttribute(flash_mma, cudaFuncAttributeMaxDynamicSharedMemorySize, 65536);
    flash_mma<<<dim3(T_DIM / 128, BH), 128, 65536>>>();

    // fork: avg_sum (DRAM-bound) runs concurrently with out-proj gemm (tensor-bound)
    cudaEventRecord(ev1, 0);
    cudaStreamWaitEvent(s2, ev1, 0);
    avg_sum<<<B_DIM * T_DIM, 256, 0, s2>>>(out + ATTN_ELEMS);
    cudaEventRecord(ev2, s2);

    gemm_mma<<<dim3(E_DIM / 64, M_ROWS / 128), 256, 98304>>>(b_out, out, 1);

    cudaStreamWaitEvent(0, ev2, 0);
}

// round 9
// speedup vs baseline: 1.0553x; 1.0553x over previous
#include <cuda_runtime.h>
#include <cuda_bf16.h>
#include <cuda_fp16.h>
#include <cstdint>
#include <math.h>

#define T_DIM 2048
#define B_DIM 4
#define E_DIM 512
#define H_DIM 8
#define HD    64
#define BH    (B_DIM*H_DIM)
#define SCALE 0.125f
#define M_ROWS (T_DIM*B_DIM)
#define ATTN_ELEMS (T_DIM*B_DIM*E_DIM)

// ---------------- scratch globals ----------------
__device__ __nv_bfloat16 g_xh[M_ROWS * E_DIM];
__device__ __nv_bfloat16 g_xl[M_ROWS * E_DIM];
__device__ __nv_bfloat16 g_wih[3 * E_DIM * E_DIM];
__device__ __nv_bfloat16 g_wil[3 * E_DIM * E_DIM];
__device__ __nv_bfloat16 g_woh[E_DIM * E_DIM];
__device__ __nv_bfloat16 g_wol[E_DIM * E_DIM];
__device__ __nv_bfloat16 g_qh[BH * T_DIM * HD];
__device__ __nv_bfloat16 g_ql[BH * T_DIM * HD];
__device__ __nv_bfloat16 g_kh[BH * T_DIM * HD];
__device__ __nv_bfloat16 g_kl[BH * T_DIM * HD];
__device__ __nv_bfloat16 g_vth[BH * HD * T_DIM];   // [bh][d][t]
__device__ __nv_bfloat16 g_vtl[BH * HD * T_DIM];
__device__ __nv_bfloat16 g_ch[M_ROWS * E_DIM];     // ctx hi  [t*B+b][e]
__device__ __nv_bfloat16 g_cl[M_ROWS * E_DIM];
__device__ float g_il[BH * T_DIM];
__device__ __align__(16) __half g_p[(size_t)BH * T_DIM * T_DIM];  // 256MB

// ---------------- helpers ----------------
__device__ __forceinline__ uint32_t smem_u32(const void* p) {
    uint32_t a;
    asm("{ .reg .u64 t; cvta.to.shared.u64 t, %1; cvt.u32.u64 %0, t; }" : "=r"(a) : "l"(p));
    return a;
}

__device__ __forceinline__ void ldsm4(uint32_t addr, uint32_t* r) {
    asm volatile("ldmatrix.sync.aligned.m8n8.x4.shared.b16 {%0,%1,%2,%3}, [%4];"
                 : "=r"(r[0]), "=r"(r[1]), "=r"(r[2]), "=r"(r[3]) : "r"(addr));
}

__device__ __forceinline__ void mma_bf(float* c, const uint32_t* a, const uint32_t* b) {
    asm volatile("mma.sync.aligned.m16n8k16.row.col.f32.bf16.bf16.f32 "
                 "{%0,%1,%2,%3},{%4,%5,%6,%7},{%8,%9},{%0,%1,%2,%3};"
                 : "+f"(c[0]), "+f"(c[1]), "+f"(c[2]), "+f"(c[3])
                 : "r"(a[0]), "r"(a[1]), "r"(a[2]), "r"(a[3]), "r"(b[0]), "r"(b[1]));
}

__device__ __forceinline__ void cpa16(uint32_t dst, const void* src) {
    asm volatile("cp.async.cg.shared.global [%0], [%1], 16;" :: "r"(dst), "l"(src));
}
#define CP_COMMIT() asm volatile("cp.async.commit_group;" ::: "memory")
#define CP_WAIT1()  asm volatile("cp.async.wait_group 1;" ::: "memory")

// tiles: rows x 64 bf16, row pitch 128B, 16B-chunk XOR swizzle
__device__ __forceinline__ uint32_t addrA(uint32_t base, int m0, int kc, int lane) {
    int g = lane >> 3, r8 = lane & 7;
    int row = m0 + r8 + ((g & 1) << 3);
    int ch  = kc + (g >> 1);
    return base + row * 128 + ((ch ^ (row & 7)) << 4);
}
__device__ __forceinline__ uint32_t addrB(uint32_t base, int n0, int kc, int lane) {
    int g = lane >> 3, r8 = lane & 7;
    int row = n0 + r8 + ((g >> 1) << 3);
    int ch  = kc + (g & 1);
    return base + row * 128 + ((ch ^ (row & 7)) << 4);
}

// 32x32 warp tile step for projection GEMMs (3 split passes)
__device__ __forceinline__ void warp_step(float c[2][4][4],
    uint32_t AHb, uint32_t ALb, uint32_t BHb, uint32_t BLb,
    int wm0, int wn0, int kc, int lane)
{
    uint32_t ah[2][4], al[2][4], bhf[4][2], blf[4][2];
    #pragma unroll
    for (int i = 0; i < 2; i++) {
        ldsm4(addrA(AHb, wm0 + i * 16, kc, lane), ah[i]);
        ldsm4(addrA(ALb, wm0 + i * 16, kc, lane), al[i]);
    }
    #pragma unroll
    for (int jj = 0; jj < 2; jj++) {
        uint32_t t[4];
        ldsm4(addrB(BHb, wn0 + jj * 16, kc, lane), t);
        bhf[jj*2][0] = t[0]; bhf[jj*2][1] = t[1];
        bhf[jj*2+1][0] = t[2]; bhf[jj*2+1][1] = t[3];
        ldsm4(addrB(BLb, wn0 + jj * 16, kc, lane), t);
        blf[jj*2][0] = t[0]; blf[jj*2][1] = t[1];
        blf[jj*2+1][0] = t[2]; blf[jj*2+1][1] = t[3];
    }
    #pragma unroll
    for (int i = 0; i < 2; i++)
        #pragma unroll
        for (int j = 0; j < 4; j++) {
            mma_bf(c[i][j], ah[i], bhf[j]);
            mma_bf(c[i][j], ah[i], blf[j]);
            mma_bf(c[i][j], al[i], bhf[j]);
        }
}

// fast hi/lo pack
__device__ __forceinline__ uint32_t packsplit2(float x, float y, uint32_t* lo) {
    __nv_bfloat162 h2 = __floats2bfloat162_rn(x, y);
    uint32_t hb = *(uint32_t*)&h2;
    float hx = __uint_as_float(hb << 16);
    float hy = __uint_as_float(hb & 0xffff0000u);
    __nv_bfloat162 l2 = __floats2bfloat162_rn(x - hx, y - hy);
    *lo = *(uint32_t*)&l2;
    return hb;
}

// ---------------- merged split kernel ----------------
#define NX  (M_ROWS * E_DIM)
#define NWI (3 * E_DIM * E_DIM)
#define NWO (E_DIM * E_DIM)
__global__ void split_all(const float* __restrict__ x,
                          const float* __restrict__ wi,
                          const float* __restrict__ wo)
{
    int i = blockIdx.x * blockDim.x + threadIdx.x;
    const float* src; __nv_bfloat16 *hi, *lo; int idx;
    if (i < NX)                { src = x;  hi = g_xh;  lo = g_xl;  idx = i; }
    else if (i < NX + NWI)     { src = wi; hi = g_wih; lo = g_wil; idx = i - NX; }
    else if (i < NX + NWI + NWO){ src = wo; hi = g_woh; lo = g_wol; idx = i - NX - NWI; }
    else return;
    float v = src[idx];
    __nv_bfloat16 h = __float2bfloat16(v);
    hi[idx] = h;
    lo[idx] = __float2bfloat16(v - __bfloat162float(h));
}

// ---------------- projection GEMM (cp.async double-buffered) ----------------
__device__ __forceinline__ void gemm_issue(uint32_t stage_base,
    const __nv_bfloat16* Ah, const __nv_bfloat16* Al,
    const __nv_bfloat16* Bh, const __nv_bfloat16* Bl,
    int m0, int n0, int ko, int tid)
{
    #pragma unroll
    for (int i = 0; i < 4; i++) {
        int idx = tid + i * 256;
        int r = idx >> 3, ch = idx & 7;
        uint32_t off = r * 128 + ((ch ^ (r & 7)) << 4);
        cpa16(stage_base + off,         Ah + (size_t)(m0 + r) * E_DIM + ko + ch * 8);
        cpa16(stage_base + 16384 + off, Al + (size_t)(m0 + r) * E_DIM + ko + ch * 8);
    }
    #pragma unroll
    for (int i = 0; i < 2; i++) {
        int idx = tid + i * 256;
        int r = idx >> 3, ch = idx & 7;
        uint32_t off = r * 128 + ((ch ^ (r & 7)) << 4);
        cpa16(stage_base + 32768 + off, Bh + (size_t)(n0 + r) * E_DIM + ko + ch * 8);
        cpa16(stage_base + 40960 + off, Bl + (size_t)(n0 + r) * E_DIM + ko + ch * 8);
    }
}

__global__ __launch_bounds__(256) void gemm_mma(const float* __restrict__ bias,
                                                float* __restrict__ C, int mode)
{
    extern __shared__ char smem[];
    const __nv_bfloat16 *Ah, *Al, *Bh, *Bl;
    if (mode == 0) { Ah = g_xh; Al = g_xl; Bh = g_wih; Bl = g_wil; }
    else           { Ah = g_ch; Al = g_cl; Bh = g_woh; Bl = g_wol; }

    const uint32_t sb = smem_u32(smem);
    const int tid = threadIdx.x, lane = tid & 31, wid = tid >> 5;
    const int wm0 = (wid & 3) * 32, wn0 = (wid >> 2) * 32;
    const int m0 = blockIdx.y * 128, n0 = blockIdx.x * 64;

    gemm_issue(sb,         Ah, Al, Bh, Bl, m0, n0, 0,  tid); CP_COMMIT();
    gemm_issue(sb + 49152, Ah, Al, Bh, Bl, m0, n0, 64, tid); CP_COMMIT();

    float c[2][4][4] = {};
    for (int s = 0; s < 8; s++) {
        CP_WAIT1();
        __syncthreads();
        uint32_t st = sb + (s & 1) * 49152;
        #pragma unroll
        for (int kc = 0; kc < 8; kc += 2)
            warp_step(c, st, st + 16384, st + 32768, st + 40960, wm0, wn0, kc, lane);
        __syncthreads();
        if (s + 2 < 8)
            gemm_issue(sb + (s & 1) * 49152, Ah, Al, Bh, Bl, m0, n0, (s + 2) * 64, tid);
        CP_COMMIT();
    }

    #pragma unroll
    for (int i = 0; i < 2; i++)
        #pragma unroll
        for (int j = 0; j < 4; j++)
            #pragma unroll
            for (int e = 0; e < 4; e++) {
                int rg = m0 + wm0 + i * 16 + (lane >> 2) + ((e >> 1) << 3);
                int n  = n0 + wn0 + j * 8 + (lane & 3) * 2 + (e & 1);
                float v = c[i][j][e] + bias[n];
                if (mode == 0) {
                    int t = rg >> 2, bb = rg & 3;
                    int sect = n >> 9, jm = n & 511;
                    int hh = jm >> 6, d = jm & 63;
                    int bh = bb * 8 + hh;
                    if (sect == 2) {
                        size_t dst = ((size_t)bh * HD + d) * T_DIM + t;
                        __nv_bfloat16 h = __float2bfloat16(v);
                        g_vth[dst] = h;
                        g_vtl[dst] = __float2bfloat16(v - __bfloat162float(h));
                    } else {
                        size_t dst = ((size_t)bh * T_DIM + t) * HD + d;
                        if (sect == 0) {
                            v *= SCALE;
                            __nv_bfloat16 h = __float2bfloat16(v);
                            g_qh[dst] = h;
                            g_ql[dst] = __float2bfloat16(v - __bfloat162float(h));
                        } else {
                            __nv_bfloat16 h = __float2bfloat16(v);
                            g_kh[dst] = h;
                            g_kl[dst] = __float2bfloat16(v - __bfloat162float(h));
                        }
                    }
                } else {
                    C[(size_t)rg * E_DIM + n] = v;
                }
            }
}

// ---------------- flash attention: 8 thin warps (16 q-rows each) ----------------
// 256 threads (8 warps), q-tile 128. Each warp: 16 q-rows x full 64-k width.
// smem: QH 0, QL 16384, KVbuf0 32768, KVbuf1 65536  (96KB, 2 CTAs/SM -> 4 warps/SMSP)
__device__ __forceinline__ void flash_issue_kv(uint32_t buf, int bh, int k0, int tid)
{
    #pragma unroll
    for (int i = 0; i < 2; i++) {
        int idx = tid + i * 256;          // 0..511
        int r = idx >> 3, ch = idx & 7;
        uint32_t off = r * 128 + ((ch ^ (r & 7)) << 4);
        const size_t kof = ((size_t)bh * T_DIM + k0 + r) * HD + ch * 8;
        const size_t vof = ((size_t)bh * HD + r) * T_DIM + k0 + ch * 8;
        cpa16(buf + off,         g_kh + kof);
        cpa16(buf + 8192 + off,  g_kl + kof);
        cpa16(buf + 16384 + off, g_vth + vof);
        cpa16(buf + 24576 + off, g_vtl + vof);
    }
}

__global__ __launch_bounds__(256, 2) void flash_mma()
{
    extern __shared__ char smem[];
    const uint32_t sb = smem_u32(smem);
    const int tid = threadIdx.x, lane = tid & 31, w = tid >> 5;
    const int bh = blockIdx.y, q0 = blockIdx.x * 128;
    const int b = bh >> 3, h = bh & 7;
    const int wq0 = w * 16;               // 16 rows per warp

    flash_issue_kv(sb + 32768, bh, 0, tid);  CP_COMMIT();
    flash_issue_kv(sb + 65536, bh, 64, tid); CP_COMMIT();

    // load Q hi/lo to smem
    {
        const __nv_bfloat16* Qh = g_qh + ((size_t)bh * T_DIM + q0) * HD;
        const __nv_bfloat16* Ql = g_ql + ((size_t)bh * T_DIM + q0) * HD;
        #pragma unroll
        for (int i = 0; i < 4; i++) {
            int idx = tid + i * 256;      // 0..1023
            int r = idx >> 3, ch = idx & 7;
            uint32_t off = r * 128 + ((ch ^ (r & 7)) << 4);
            *(uint4*)(smem + off)         = *(const uint4*)(Qh + (size_t)r * HD + ch * 8);
            *(uint4*)(smem + 16384 + off) = *(const uint4*)(Ql + (size_t)r * HD + ch * 8);
        }
    }
    __syncthreads();

    // cache Q fragments (16 rows x 64 k per warp)
    uint32_t qh[4][4], ql[4][4];
    #pragma unroll
    for (int kk = 0; kk < 4; kk++) {
        ldsm4(addrA(sb,         wq0, 2 * kk, lane), qh[kk]);
        ldsm4(addrA(sb + 16384, wq0, 2 * kk, lane), ql[kk]);
    }

    float o[8][4] = {};
    float rs[2] = {};
    const int r0base = q0 + wq0 + (lane >> 2);

    for (int kt = 0; kt < T_DIM / 64; kt++) {
        CP_WAIT1();
        __syncthreads();
        const uint32_t buf = sb + 32768 + (kt & 1) * 32768;

        // S = Q K^T  (16 x 64 per warp)
        float s[8][4] = {};
        #pragma unroll
        for (int kk = 0; kk < 4; kk++)
            #pragma unroll
            for (int jj = 0; jj < 4; jj++) {
                uint32_t th[4], tl[4];
                ldsm4(addrB(buf,        jj * 16, 2 * kk, lane), th);
                ldsm4(addrB(buf + 8192, jj * 16, 2 * kk, lane), tl);
                uint32_t bh0[2] = {th[0], th[1]}, bh1[2] = {th[2], th[3]};
                uint32_t bl0[2] = {tl[0], tl[1]}, bl1[2] = {tl[2], tl[3]};
                mma_bf(s[jj*2], qh[kk], bh0);
                mma_bf(s[jj*2], qh[kk], bl0);
                mma_bf(s[jj*2], ql[kk], bh0);
                mma_bf(s[jj*2+1], qh[kk], bh1);
                mma_bf(s[jj*2+1], qh[kk], bl1);
                mma_bf(s[jj*2+1], ql[kk], bh1);
            }

        // exp (MUFU) + row sums + stream P to gmem
        #pragma unroll
        for (int j = 0; j < 8; j++) {
            float p0 = __expf(s[j][0]), p1 = __expf(s[j][1]);
            float p2 = __expf(s[j][2]), p3 = __expf(s[j][3]);
            s[j][0] = p0; s[j][1] = p1; s[j][2] = p2; s[j][3] = p3;
            rs[0] += p0 + p1;
            rs[1] += p2 + p3;
            int col = kt * 64 + j * 8 + (lane & 3) * 2;
            __stcs((__half2*)(g_p + ((size_t)bh * T_DIM + r0base) * T_DIM + col),
                   __floats2half2_rn(p0, p1));
            __stcs((__half2*)(g_p + ((size_t)bh * T_DIM + r0base + 8) * T_DIM + col),
                   __floats2half2_rn(p2, p3));
        }

        // pack P into PV A-fragments (registers only)
        uint32_t aPh[4][4], aPl[4][4];
        #pragma unroll
        for (int kk = 0; kk < 4; kk++) {
            aPh[kk][0] = packsplit2(s[2*kk][0],   s[2*kk][1],   &aPl[kk][0]);
            aPh[kk][1] = packsplit2(s[2*kk][2],   s[2*kk][3],   &aPl[kk][1]);
            aPh[kk][2] = packsplit2(s[2*kk+1][0], s[2*kk+1][1], &aPl[kk][2]);
            aPh[kk][3] = packsplit2(s[2*kk+1][2], s[2*kk+1][3], &aPl[kk][3]);
        }

        // O += P V  (B = Vt in smem)
        #pragma unroll
        for (int kk = 0; kk < 4; kk++)
            #pragma unroll
            for (int jj = 0; jj < 4; jj++) {
                uint32_t th[4], tl[4];
                ldsm4(addrB(buf + 16384, jj * 16, 2 * kk, lane), th);
                ldsm4(addrB(buf + 24576, jj * 16, 2 * kk, lane), tl);
                uint32_t bh0[2] = {th[0], th[1]}, bh1[2] = {th[2], th[3]};
                uint32_t bl0[2] = {tl[0], tl[1]}, bl1[2] = {tl[2], tl[3]};
                mma_bf(o[jj*2], aPh[kk], bh0);
                mma_bf(o[jj*2], aPh[kk], bl0);
                mma_bf(o[jj*2], aPl[kk], bh0);
                mma_bf(o[jj*2+1], aPh[kk], bh1);
                mma_bf(o[jj*2+1], aPh[kk], bl1);
                mma_bf(o[jj*2+1], aPl[kk], bh1);
            }
        __syncthreads();
        if (kt + 2 < T_DIM / 64)
            flash_issue_kv(sb + 32768 + (kt & 1) * 32768, bh, (kt + 2) * 64, tid);
        CP_COMMIT();
    }

    // quad-reduce row sums
    #pragma unroll
    for (int x = 0; x < 2; x++) {
        rs[x] += __shfl_xor_sync(0xffffffffu, rs[x], 1);
        rs[x] += __shfl_xor_sync(0xffffffffu, rs[x], 2);
    }
    float il[2] = {1.0f / rs[0], 1.0f / rs[1]};

    // write ctx (bf16 hi/lo) and 1/l
    #pragma unroll
    for (int hf = 0; hf < 2; hf++) {
        int r = wq0 + (lane >> 2) + hf * 8;
        float s_il = il[hf];
        #pragma unroll
        for (int j = 0; j < 8; j++) {
            int cc = j * 8 + (lane & 3) * 2;
            uint32_t lo;
            uint32_t hi = packsplit2(o[j][hf*2] * s_il, o[j][hf*2+1] * s_il, &lo);
            size_t off = ((size_t)(q0 + r) * B_DIM + b) * E_DIM + h * HD + cc;
            *(uint32_t*)&g_ch[off] = hi;
            *(uint32_t*)&g_cl[off] = lo;
        }
        if ((lane & 3) == 0)
            g_il[(size_t)bh * T_DIM + q0 + r] = s_il;
    }
}

// ---------------- avg_weights: pure memory pass over stored P ----------------
__global__ __launch_bounds__(256) void avg_sum(float* __restrict__ outAvg)
{
    const int blk = blockIdx.x;
    const int b = blk >> 11, q = blk & 2047;
    const int tid = threadIdx.x;

    float acc[8] = {};
    #pragma unroll
    for (int hh = 0; hh < H_DIM; hh++) {
        const int bh = b * 8 + hh;
        float il = g_il[(size_t)bh * T_DIM + q] * 0.125f;
        uint4 u = *((const uint4*)(g_p + ((size_t)bh * T_DIM + q) * T_DIM) + tid);
        __half2* hp = (__half2*)&u;
        #pragma unroll
        for (int c = 0; c < 4; c++) {
            float2 f = __half22float2(hp[c]);
            acc[c*2]   = fmaf(f.x, il, acc[c*2]);
            acc[c*2+1] = fmaf(f.y, il, acc[c*2+1]);
        }
    }
    float* dst = outAvg + ((size_t)b * T_DIM + q) * T_DIM + tid * 8;
    *(float4*)dst       = make_float4(acc[0], acc[1], acc[2], acc[3]);
    *(float4*)(dst + 4) = make_float4(acc[4], acc[5], acc[6], acc[7]);
}

// ---------------- launch ----------------
extern "C" void kernel_launch(void* const* d_in, const int* in_sizes, int n_in,
                              void* d_out, int out_size)
{
    const float* x     = (const float*)d_in[0];
    const float* w_in  = (const float*)d_in[1];
    const float* b_in  = (const float*)d_in[2];
    const float* w_out = (const float*)d_in[3];
    const float* b_out = (const float*)d_in[4];
    float* out = (float*)d_out;

    static cudaStream_t s2 = nullptr;
    static cudaEvent_t ev1 = nullptr, ev2 = nullptr;
    if (!s2) {
        cudaStreamCreateWithFlags(&s2, cudaStreamNonBlocking);
        cudaEventCreateWithFlags(&ev1, cudaEventDisableTiming);
        cudaEventCreateWithFlags(&ev2, cudaEventDisableTiming);
    }

    split_all<<<(NX + NWI + NWO + 255) / 256, 256>>>(x, w_in, w_out);

    cudaFuncSetAttribute(gemm_mma, cudaFuncAttributeMaxDynamicSharedMemorySize, 98304);
    gemm_mma<<<dim3(3 * E_DIM / 64, M_ROWS / 128), 256, 98304>>>(b_in, out, 0);

    cudaFuncSetAttribute(flash_mma, cudaFuncAttributeMaxDynamicSharedMemorySize, 98304);
    flash_mma<<<dim3(T_DIM / 128, BH), 256, 98304>>>();

    // fork: avg_sum (DRAM-bound) runs concurrently with out-proj gemm (tensor-bound)
    cudaEventRecord(ev1, 0);
    cudaStreamWaitEvent(s2, ev1, 0);
    avg_sum<<<B_DIM * T_DIM, 256, 0, s2>>>(out + ATTN_ELEMS);
    cudaEventRecord(ev2, s2);

    gemm_mma<<<dim3(E_DIM / 64, M_ROWS / 128), 256, 98304>>>(b_out, out, 1);

    cudaStreamWaitEvent(0, ev2, 0);
}

// round 10
// speedup vs baseline: 1.0849x; 1.0281x over previous
#include <cuda_runtime.h>
#include <cuda_bf16.h>
#include <cuda_fp16.h>
#include <cstdint>
#include <math.h>

#define T_DIM 2048
#define B_DIM 4
#define E_DIM 512
#define H_DIM 8
#define HD    64
#define BH    (B_DIM*H_DIM)
#define SCALE 0.125f
#define M_ROWS (T_DIM*B_DIM)
#define ATTN_ELEMS (T_DIM*B_DIM*E_DIM)

// ---------------- scratch globals ----------------
__device__ __nv_bfloat16 g_xh[M_ROWS * E_DIM];
__device__ __nv_bfloat16 g_xl[M_ROWS * E_DIM];
__device__ __nv_bfloat16 g_wih[3 * E_DIM * E_DIM];
__device__ __nv_bfloat16 g_wil[3 * E_DIM * E_DIM];
__device__ __nv_bfloat16 g_woh[E_DIM * E_DIM];
__device__ __nv_bfloat16 g_wol[E_DIM * E_DIM];
__device__ __nv_bfloat16 g_qh[BH * T_DIM * HD];
__device__ __nv_bfloat16 g_ql[BH * T_DIM * HD];
__device__ __nv_bfloat16 g_kh[BH * T_DIM * HD];
__device__ __nv_bfloat16 g_kl[BH * T_DIM * HD];
__device__ __nv_bfloat16 g_vth[BH * HD * T_DIM];   // [bh][d][t]
__device__ __nv_bfloat16 g_vtl[BH * HD * T_DIM];
__device__ __nv_bfloat16 g_ch[M_ROWS * E_DIM];     // ctx hi  [t*B+b][e]
__device__ __nv_bfloat16 g_cl[M_ROWS * E_DIM];
__device__ float g_il[BH * T_DIM];
__device__ __align__(16) __half g_p[(size_t)BH * T_DIM * T_DIM];  // 256MB

// ---------------- helpers ----------------
__device__ __forceinline__ uint32_t smem_u32(const void* p) {
    uint32_t a;
    asm("{ .reg .u64 t; cvta.to.shared.u64 t, %1; cvt.u32.u64 %0, t; }" : "=r"(a) : "l"(p));
    return a;
}

__device__ __forceinline__ void ldsm4(uint32_t addr, uint32_t* r) {
    asm volatile("ldmatrix.sync.aligned.m8n8.x4.shared.b16 {%0,%1,%2,%3}, [%4];"
                 : "=r"(r[0]), "=r"(r[1]), "=r"(r[2]), "=r"(r[3]) : "r"(addr));
}

__device__ __forceinline__ void mma_bf(float* c, const uint32_t* a, const uint32_t* b) {
    asm volatile("mma.sync.aligned.m16n8k16.row.col.f32.bf16.bf16.f32 "
                 "{%0,%1,%2,%3},{%4,%5,%6,%7},{%8,%9},{%0,%1,%2,%3};"
                 : "+f"(c[0]), "+f"(c[1]), "+f"(c[2]), "+f"(c[3])
                 : "r"(a[0]), "r"(a[1]), "r"(a[2]), "r"(a[3]), "r"(b[0]), "r"(b[1]));
}

__device__ __forceinline__ void cpa16(uint32_t dst, const void* src) {
    asm volatile("cp.async.cg.shared.global [%0], [%1], 16;" :: "r"(dst), "l"(src));
}
#define CP_COMMIT() asm volatile("cp.async.commit_group;" ::: "memory")
#define CP_WAIT1()  asm volatile("cp.async.wait_group 1;" ::: "memory")

// tiles: rows x 64 bf16, row pitch 128B, 16B-chunk XOR swizzle
__device__ __forceinline__ uint32_t addrA(uint32_t base, int m0, int kc, int lane) {
    int g = lane >> 3, r8 = lane & 7;
    int row = m0 + r8 + ((g & 1) << 3);
    int ch  = kc + (g >> 1);
    return base + row * 128 + ((ch ^ (row & 7)) << 4);
}
__device__ __forceinline__ uint32_t addrB(uint32_t base, int n0, int kc, int lane) {
    int g = lane >> 3, r8 = lane & 7;
    int row = n0 + r8 + ((g >> 1) << 3);
    int ch  = kc + (g & 1);
    return base + row * 128 + ((ch ^ (row & 7)) << 4);
}

// fast hi/lo pack
__device__ __forceinline__ uint32_t packsplit2(float x, float y, uint32_t* lo) {
    __nv_bfloat162 h2 = __floats2bfloat162_rn(x, y);
    uint32_t hb = *(uint32_t*)&h2;
    float hx = __uint_as_float(hb << 16);
    float hy = __uint_as_float(hb & 0xffff0000u);
    __nv_bfloat162 l2 = __floats2bfloat162_rn(x - hx, y - hy);
    *lo = *(uint32_t*)&l2;
    return hb;
}

// ---------------- merged split kernel ----------------
#define NX  (M_ROWS * E_DIM)
#define NWI (3 * E_DIM * E_DIM)
#define NWO (E_DIM * E_DIM)
__global__ void split_all(const float* __restrict__ x,
                          const float* __restrict__ wi,
                          const float* __restrict__ wo)
{
    int i = blockIdx.x * blockDim.x + threadIdx.x;
    const float* src; __nv_bfloat16 *hi, *lo; int idx;
    if (i < NX)                { src = x;  hi = g_xh;  lo = g_xl;  idx = i; }
    else if (i < NX + NWI)     { src = wi; hi = g_wih; lo = g_wil; idx = i - NX; }
    else if (i < NX + NWI + NWO){ src = wo; hi = g_woh; lo = g_wol; idx = i - NX - NWI; }
    else return;
    float v = src[idx];
    __nv_bfloat16 h = __float2bfloat16(v);
    hi[idx] = h;
    lo[idx] = __float2bfloat16(v - __bfloat162float(h));
}

// ---------------- projection GEMM: 128x128 CTA tile, 32x64 warp tile ----------------
// stage layout: AH 0, AL 16384, BH 32768, BL 49152  (stage 65536, 2 stages = 128KB)
__device__ __forceinline__ void gemm_issue(uint32_t stage_base,
    const __nv_bfloat16* Ah, const __nv_bfloat16* Al,
    const __nv_bfloat16* Bh, const __nv_bfloat16* Bl,
    int m0, int n0, int ko, int tid)
{
    #pragma unroll
    for (int i = 0; i < 4; i++) {
        int idx = tid + i * 256;          // 0..1023
        int r = idx >> 3, ch = idx & 7;
        uint32_t off = r * 128 + ((ch ^ (r & 7)) << 4);
        cpa16(stage_base + off,         Ah + (size_t)(m0 + r) * E_DIM + ko + ch * 8);
        cpa16(stage_base + 16384 + off, Al + (size_t)(m0 + r) * E_DIM + ko + ch * 8);
        cpa16(stage_base + 32768 + off, Bh + (size_t)(n0 + r) * E_DIM + ko + ch * 8);
        cpa16(stage_base + 49152 + off, Bl + (size_t)(n0 + r) * E_DIM + ko + ch * 8);
    }
}

__global__ __launch_bounds__(256) void gemm_mma(const float* __restrict__ bias,
                                                float* __restrict__ C, int mode)
{
    extern __shared__ char smem[];
    const __nv_bfloat16 *Ah, *Al, *Bh, *Bl;
    if (mode == 0) { Ah = g_xh; Al = g_xl; Bh = g_wih; Bl = g_wil; }
    else           { Ah = g_ch; Al = g_cl; Bh = g_woh; Bl = g_wol; }

    const uint32_t sb = smem_u32(smem);
    const int tid = threadIdx.x, lane = tid & 31, wid = tid >> 5;
    const int wm0 = (wid & 3) * 32, wn0 = (wid >> 2) * 64;
    const int m0 = blockIdx.y * 128, n0 = blockIdx.x * 128;

    gemm_issue(sb,         Ah, Al, Bh, Bl, m0, n0, 0,  tid); CP_COMMIT();
    gemm_issue(sb + 65536, Ah, Al, Bh, Bl, m0, n0, 64, tid); CP_COMMIT();

    float c[2][8][4] = {};
    for (int s = 0; s < 8; s++) {
        CP_WAIT1();
        __syncthreads();
        uint32_t st = sb + (s & 1) * 65536;
        #pragma unroll
        for (int kc = 0; kc < 8; kc += 2) {
            uint32_t ah[2][4], al[2][4], bhf[8][2], blf[8][2];
            #pragma unroll
            for (int i = 0; i < 2; i++) {
                ldsm4(addrA(st,         wm0 + i * 16, kc, lane), ah[i]);
                ldsm4(addrA(st + 16384, wm0 + i * 16, kc, lane), al[i]);
            }
            #pragma unroll
            for (int jj = 0; jj < 4; jj++) {
                uint32_t t[4];
                ldsm4(addrB(st + 32768, wn0 + jj * 16, kc, lane), t);
                bhf[jj*2][0] = t[0]; bhf[jj*2][1] = t[1];
                bhf[jj*2+1][0] = t[2]; bhf[jj*2+1][1] = t[3];
                ldsm4(addrB(st + 49152, wn0 + jj * 16, kc, lane), t);
                blf[jj*2][0] = t[0]; blf[jj*2][1] = t[1];
                blf[jj*2+1][0] = t[2]; blf[jj*2+1][1] = t[3];
            }
            #pragma unroll
            for (int i = 0; i < 2; i++)
                #pragma unroll
                for (int j = 0; j < 8; j++) {
                    mma_bf(c[i][j], ah[i], bhf[j]);
                    mma_bf(c[i][j], ah[i], blf[j]);
                    mma_bf(c[i][j], al[i], bhf[j]);
                }
        }
        __syncthreads();
        if (s + 2 < 8)
            gemm_issue(sb + (s & 1) * 65536, Ah, Al, Bh, Bl, m0, n0, (s + 2) * 64, tid);
        CP_COMMIT();
    }

    #pragma unroll
    for (int i = 0; i < 2; i++)
        #pragma unroll
        for (int j = 0; j < 8; j++)
            #pragma unroll
            for (int e = 0; e < 4; e++) {
                int rg = m0 + wm0 + i * 16 + (lane >> 2) + ((e >> 1) << 3);
                int n  = n0 + wn0 + j * 8 + (lane & 3) * 2 + (e & 1);
                float v = c[i][j][e] + bias[n];
                if (mode == 0) {
                    int t = rg >> 2, bb = rg & 3;
                    int sect = n >> 9, jm = n & 511;
                    int hh = jm >> 6, d = jm & 63;
                    int bh = bb * 8 + hh;
                    if (sect == 2) {
                        size_t dst = ((size_t)bh * HD + d) * T_DIM + t;
                        __nv_bfloat16 h = __float2bfloat16(v);
                        g_vth[dst] = h;
                        g_vtl[dst] = __float2bfloat16(v - __bfloat162float(h));
                    } else {
                        size_t dst = ((size_t)bh * T_DIM + t) * HD + d;
                        if (sect == 0) {
                            v *= SCALE;
                            __nv_bfloat16 h = __float2bfloat16(v);
                            g_qh[dst] = h;
                            g_ql[dst] = __float2bfloat16(v - __bfloat162float(h));
                        } else {
                            __nv_bfloat16 h = __float2bfloat16(v);
                            g_kh[dst] = h;
                            g_kl[dst] = __float2bfloat16(v - __bfloat162float(h));
                        }
                    }
                } else {
                    C[(size_t)rg * E_DIM + n] = v;
                }
            }
}

// ---------------- flash attention: R6 winner (phase-separated, 4 fat warps) --------
// 128 threads (4 warps), q-tile 128 (32 rows/warp, full k width per warp).
// smem: QH 0, QL 16384, KVbuf0 32768, KVbuf1 65536
__device__ __forceinline__ void flash_issue_kv(uint32_t buf, int bh, int k0, int tid)
{
    #pragma unroll
    for (int i = 0; i < 4; i++) {
        int idx = tid + i * 128;
        int r = idx >> 3, ch = idx & 7;
        uint32_t off = r * 128 + ((ch ^ (r & 7)) << 4);
        const size_t kof = ((size_t)bh * T_DIM + k0 + r) * HD + ch * 8;
        const size_t vof = ((size_t)bh * HD + r) * T_DIM + k0 + ch * 8;
        cpa16(buf + off,         g_kh + kof);
        cpa16(buf + 8192 + off,  g_kl + kof);
        cpa16(buf + 16384 + off, g_vth + vof);
        cpa16(buf + 24576 + off, g_vtl + vof);
    }
}

__global__ __launch_bounds__(128, 2) void flash_mma()
{
    extern __shared__ char smem[];
    const uint32_t sb = smem_u32(smem);
    const int tid = threadIdx.x, lane = tid & 31, w = tid >> 5;
    const int bh = blockIdx.y, q0 = blockIdx.x * 128;
    const int b = bh >> 3, h = bh & 7;
    const int wq0 = w * 32;

    flash_issue_kv(sb + 32768, bh, 0, tid);  CP_COMMIT();
    flash_issue_kv(sb + 65536, bh, 64, tid); CP_COMMIT();

    {
        const __nv_bfloat16* Qh = g_qh + ((size_t)bh * T_DIM + q0) * HD;
        const __nv_bfloat16* Ql = g_ql + ((size_t)bh * T_DIM + q0) * HD;
        #pragma unroll
        for (int i = 0; i < 8; i++) {
            int idx = tid + i * 128;
            int r = idx >> 3, ch = idx & 7;
            uint32_t off = r * 128 + ((ch ^ (r & 7)) << 4);
            *(uint4*)(smem + off)         = *(const uint4*)(Qh + (size_t)r * HD + ch * 8);
            *(uint4*)(smem + 16384 + off) = *(const uint4*)(Ql + (size_t)r * HD + ch * 8);
        }
    }
    __syncthreads();

    uint32_t qh[2][4][4], ql[2][4][4];
    #pragma unroll
    for (int i = 0; i < 2; i++)
        #pragma unroll
        for (int kk = 0; kk < 4; kk++) {
            ldsm4(addrA(sb,         wq0 + i * 16, 2 * kk, lane), qh[i][kk]);
            ldsm4(addrA(sb + 16384, wq0 + i * 16, 2 * kk, lane), ql[i][kk]);
        }

    float o[2][8][4] = {};
    float rs[4] = {};

    for (int kt = 0; kt < T_DIM / 64; kt++) {
        CP_WAIT1();
        __syncthreads();
        const uint32_t buf = sb + 32768 + (kt & 1) * 32768;

        // S = Q K^T  (32 x 64 per warp)
        float s[2][8][4] = {};
        #pragma unroll
        for (int kk = 0; kk < 4; kk++)
            #pragma unroll
            for (int jj = 0; jj < 4; jj++) {
                uint32_t th[4], tl[4];
                ldsm4(addrB(buf,        jj * 16, 2 * kk, lane), th);
                ldsm4(addrB(buf + 8192, jj * 16, 2 * kk, lane), tl);
                uint32_t bh0[2] = {th[0], th[1]}, bh1[2] = {th[2], th[3]};
                uint32_t bl0[2] = {tl[0], tl[1]}, bl1[2] = {tl[2], tl[3]};
                #pragma unroll
                for (int i = 0; i < 2; i++) {
                    mma_bf(s[i][jj*2], qh[i][kk], bh0);
                    mma_bf(s[i][jj*2], qh[i][kk], bl0);
                    mma_bf(s[i][jj*2], ql[i][kk], bh0);
                    mma_bf(s[i][jj*2+1], qh[i][kk], bh1);
                    mma_bf(s[i][jj*2+1], qh[i][kk], bl1);
                    mma_bf(s[i][jj*2+1], ql[i][kk], bh1);
                }
            }

        // exp (MUFU) + row sums + stream P to gmem
        #pragma unroll
        for (int i = 0; i < 2; i++)
            #pragma unroll
            for (int j = 0; j < 8; j++) {
                float p0 = __expf(s[i][j][0]), p1 = __expf(s[i][j][1]);
                float p2 = __expf(s[i][j][2]), p3 = __expf(s[i][j][3]);
                s[i][j][0] = p0; s[i][j][1] = p1; s[i][j][2] = p2; s[i][j][3] = p3;
                rs[i*2]   += p0 + p1;
                rs[i*2+1] += p2 + p3;
                int col = kt * 64 + j * 8 + (lane & 3) * 2;
                int r0 = q0 + wq0 + i * 16 + (lane >> 2);
                __stcs((__half2*)(g_p + ((size_t)bh * T_DIM + r0) * T_DIM + col),
                       __floats2half2_rn(p0, p1));
                __stcs((__half2*)(g_p + ((size_t)bh * T_DIM + r0 + 8) * T_DIM + col),
                       __floats2half2_rn(p2, p3));
            }

        // pack P into PV A-fragments (registers only)
        uint32_t aPh[2][4][4], aPl[2][4][4];
        #pragma unroll
        for (int i = 0; i < 2; i++)
            #pragma unroll
            for (int kk = 0; kk < 4; kk++) {
                aPh[i][kk][0] = packsplit2(s[i][2*kk][0],   s[i][2*kk][1],   &aPl[i][kk][0]);
                aPh[i][kk][1] = packsplit2(s[i][2*kk][2],   s[i][2*kk][3],   &aPl[i][kk][1]);
                aPh[i][kk][2] = packsplit2(s[i][2*kk+1][0], s[i][2*kk+1][1], &aPl[i][kk][2]);
                aPh[i][kk][3] = packsplit2(s[i][2*kk+1][2], s[i][2*kk+1][3], &aPl[i][kk][3]);
            }

        // O += P V  (B = Vt in smem)
        #pragma unroll
        for (int kk = 0; kk < 4; kk++)
            #pragma unroll
            for (int jj = 0; jj < 4; jj++) {
                uint32_t th[4], tl[4];
                ldsm4(addrB(buf + 16384, jj * 16, 2 * kk, lane), th);
                ldsm4(addrB(buf + 24576, jj * 16, 2 * kk, lane), tl);
                uint32_t bh0[2] = {th[0], th[1]}, bh1[2] = {th[2], th[3]};
                uint32_t bl0[2] = {tl[0], tl[1]}, bl1[2] = {tl[2], tl[3]};
                #pragma unroll
                for (int i = 0; i < 2; i++) {
                    mma_bf(o[i][jj*2], aPh[i][kk], bh0);
                    mma_bf(o[i][jj*2], aPh[i][kk], bl0);
                    mma_bf(o[i][jj*2], aPl[i][kk], bh0);
                    mma_bf(o[i][jj*2+1], aPh[i][kk], bh1);
                    mma_bf(o[i][jj*2+1], aPh[i][kk], bl1);
                    mma_bf(o[i][jj*2+1], aPl[i][kk], bh1);
                }
            }
        __syncthreads();
        if (kt + 2 < T_DIM / 64)
            flash_issue_kv(sb + 32768 + (kt & 1) * 32768, bh, (kt + 2) * 64, tid);
        CP_COMMIT();
    }

    #pragma unroll
    for (int x = 0; x < 4; x++) {
        rs[x] += __shfl_xor_sync(0xffffffffu, rs[x], 1);
        rs[x] += __shfl_xor_sync(0xffffffffu, rs[x], 2);
    }
    float il[4] = {1.0f / rs[0], 1.0f / rs[1], 1.0f / rs[2], 1.0f / rs[3]};

    #pragma unroll
    for (int i = 0; i < 2; i++)
        #pragma unroll
        for (int hf = 0; hf < 2; hf++) {
            int r = wq0 + i * 16 + (lane >> 2) + hf * 8;
            float s_il = il[i*2 + hf];
            #pragma unroll
            for (int j = 0; j < 8; j++) {
                int cc = j * 8 + (lane & 3) * 2;
                uint32_t lo;
                uint32_t hi = packsplit2(o[i][j][hf*2] * s_il, o[i][j][hf*2+1] * s_il, &lo);
                size_t off = ((size_t)(q0 + r) * B_DIM + b) * E_DIM + h * HD + cc;
                *(uint32_t*)&g_ch[off] = hi;
                *(uint32_t*)&g_cl[off] = lo;
            }
            if ((lane & 3) == 0)
                g_il[(size_t)bh * T_DIM + q0 + r] = s_il;
        }
}

// ---------------- avg_weights: pure memory pass over stored P ----------------
__global__ __launch_bounds__(256) void avg_sum(float* __restrict__ outAvg)
{
    const int blk = blockIdx.x;
    const int b = blk >> 11, q = blk & 2047;
    const int tid = threadIdx.x;

    float acc[8] = {};
    #pragma unroll
    for (int hh = 0; hh < H_DIM; hh++) {
        const int bh = b * 8 + hh;
        float il = g_il[(size_t)bh * T_DIM + q] * 0.125f;
        uint4 u = *((const uint4*)(g_p + ((size_t)bh * T_DIM + q) * T_DIM) + tid);
        __half2* hp = (__half2*)&u;
        #pragma unroll
        for (int c = 0; c < 4; c++) {
            float2 f = __half22float2(hp[c]);
            acc[c*2]   = fmaf(f.x, il, acc[c*2]);
            acc[c*2+1] = fmaf(f.y, il, acc[c*2+1]);
        }
    }
    float* dst = outAvg + ((size_t)b * T_DIM + q) * T_DIM + tid * 8;
    *(float4*)dst       = make_float4(acc[0], acc[1], acc[2], acc[3]);
    *(float4*)(dst + 4) = make_float4(acc[4], acc[5], acc[6], acc[7]);
}

// ---------------- launch ----------------
extern "C" void kernel_launch(void* const* d_in, const int* in_sizes, int n_in,
                              void* d_out, int out_size)
{
    const float* x     = (const float*)d_in[0];
    const float* w_in  = (const float*)d_in[1];
    const float* b_in  = (const float*)d_in[2];
    const float* w_out = (const float*)d_in[3];
    const float* b_out = (const float*)d_in[4];
    float* out = (float*)d_out;

    static cudaStream_t s2 = nullptr;
    static cudaEvent_t ev1 = nullptr, ev2 = nullptr;
    if (!s2) {
        cudaStreamCreateWithFlags(&s2, cudaStreamNonBlocking);
        cudaEventCreateWithFlags(&ev1, cudaEventDisableTiming);
        cudaEventCreateWithFlags(&ev2, cudaEventDisableTiming);
    }

    split_all<<<(NX + NWI + NWO + 255) / 256, 256>>>(x, w_in, w_out);

    cudaFuncSetAttribute(gemm_mma, cudaFuncAttributeMaxDynamicSharedMemorySize, 131072);
    gemm_mma<<<dim3(3 * E_DIM / 128, M_ROWS / 128), 256, 131072>>>(b_in, out, 0);

    cudaFuncSetAttribute(flash_mma, cudaFuncAttributeMaxDynamicSharedMemorySize, 98304);
    flash_mma<<<dim3(T_DIM / 128, BH), 128, 98304>>>();

    // fork: avg_sum (DRAM-bound) runs concurrently with out-proj gemm (tensor-bound)
    cudaEventRecord(ev1, 0);
    cudaStreamWaitEvent(s2, ev1, 0);
    avg_sum<<<B_DIM * T_DIM, 256, 0, s2>>>(out + ATTN_ELEMS);
    cudaEventRecord(ev2, s2);

    gemm_mma<<<dim3(E_DIM / 128, M_ROWS / 128), 256, 131072>>>(b_out, out, 1);

    cudaStreamWaitEvent(0, ev2, 0);
}

// round 11
// speedup vs baseline: 1.4303x; 1.3184x over previous
#include <cuda_runtime.h>
#include <cuda_bf16.h>
#include <cuda_fp16.h>
#include <cstdint>
#include <math.h>

#define T_DIM 2048
#define B_DIM 4
#define E_DIM 512
#define H_DIM 8
#define HD    64
#define BH    (B_DIM*H_DIM)
#define SCALE 0.125f
#define M_ROWS (T_DIM*B_DIM)
#define ATTN_ELEMS (T_DIM*B_DIM*E_DIM)

// ---------------- scratch globals (fp16 hi/lo split; B-side operands hi-only) ---
__device__ __half g_xh[M_ROWS * E_DIM];
__device__ __half g_xl[M_ROWS * E_DIM];
__device__ __half g_wih[3 * E_DIM * E_DIM];          // hi only
__device__ __half g_woh[E_DIM * E_DIM];              // hi only
__device__ __half g_qh[BH * T_DIM * HD];
__device__ __half g_ql[BH * T_DIM * HD];
__device__ __half g_kh[BH * T_DIM * HD];             // hi only
__device__ __half g_vth[BH * HD * T_DIM];            // [bh][d][t], hi only
__device__ __half g_ch[M_ROWS * E_DIM];              // ctx hi  [t*B+b][e]
__device__ __half g_cl[M_ROWS * E_DIM];
__device__ float g_il[BH * T_DIM];
__device__ __align__(16) __half g_p[(size_t)BH * T_DIM * T_DIM];  // 256MB

// ---------------- helpers ----------------
__device__ __forceinline__ uint32_t smem_u32(const void* p) {
    uint32_t a;
    asm("{ .reg .u64 t; cvta.to.shared.u64 t, %1; cvt.u32.u64 %0, t; }" : "=r"(a) : "l"(p));
    return a;
}

__device__ __forceinline__ void ldsm4(uint32_t addr, uint32_t* r) {
    asm volatile("ldmatrix.sync.aligned.m8n8.x4.shared.b16 {%0,%1,%2,%3}, [%4];"
                 : "=r"(r[0]), "=r"(r[1]), "=r"(r[2]), "=r"(r[3]) : "r"(addr));
}

__device__ __forceinline__ void mma_h(float* c, const uint32_t* a, const uint32_t* b) {
    asm volatile("mma.sync.aligned.m16n8k16.row.col.f32.f16.f16.f32 "
                 "{%0,%1,%2,%3},{%4,%5,%6,%7},{%8,%9},{%0,%1,%2,%3};"
                 : "+f"(c[0]), "+f"(c[1]), "+f"(c[2]), "+f"(c[3])
                 : "r"(a[0]), "r"(a[1]), "r"(a[2]), "r"(a[3]), "r"(b[0]), "r"(b[1]));
}

__device__ __forceinline__ void cpa16(uint32_t dst, const void* src) {
    asm volatile("cp.async.cg.shared.global [%0], [%1], 16;" :: "r"(dst), "l"(src));
}
#define CP_COMMIT() asm volatile("cp.async.commit_group;" ::: "memory")
#define CP_WAIT1()  asm volatile("cp.async.wait_group 1;" ::: "memory")

// tiles: rows x 64 fp16, row pitch 128B, 16B-chunk XOR swizzle
__device__ __forceinline__ uint32_t addrA(uint32_t base, int m0, int kc, int lane) {
    int g = lane >> 3, r8 = lane & 7;
    int row = m0 + r8 + ((g & 1) << 3);
    int ch  = kc + (g >> 1);
    return base + row * 128 + ((ch ^ (row & 7)) << 4);
}
__device__ __forceinline__ uint32_t addrB(uint32_t base, int n0, int kc, int lane) {
    int g = lane >> 3, r8 = lane & 7;
    int row = n0 + r8 + ((g >> 1) << 3);
    int ch  = kc + (g & 1);
    return base + row * 128 + ((ch ^ (row & 7)) << 4);
}

// fp16 hi/lo pack: hi = rn fp16x2 of (x,y); lo = residual, rn fp16x2
__device__ __forceinline__ uint32_t packsplit_h(float x, float y, uint32_t* lo) {
    __half2 h2 = __floats2half2_rn(x, y);
    float hx = __low2float(h2), hy = __high2float(h2);
    __half2 l2 = __floats2half2_rn(x - hx, y - hy);
    *lo = *(uint32_t*)&l2;
    return *(uint32_t*)&h2;
}

// ---------------- merged split kernel ----------------
#define NX  (M_ROWS * E_DIM)
#define NWI (3 * E_DIM * E_DIM)
#define NWO (E_DIM * E_DIM)
__global__ void split_all(const float* __restrict__ x,
                          const float* __restrict__ wi,
                          const float* __restrict__ wo)
{
    int i = blockIdx.x * blockDim.x + threadIdx.x;
    if (i < NX) {
        float v = x[i];
        __half h = __float2half_rn(v);
        g_xh[i] = h;
        g_xl[i] = __float2half_rn(v - __half2float(h));
    } else if (i < NX + NWI) {
        g_wih[i - NX] = __float2half_rn(wi[i - NX]);
    } else if (i < NX + NWI + NWO) {
        g_woh[i - NX - NWI] = __float2half_rn(wo[i - NX - NWI]);
    }
}

// ---------------- projection GEMM: 128x64 CTA tile, 2-pass fp16 split ------------
// stage layout: AH 0 (16KB), AL 16384 (16KB), BH 32768 (8KB); stage size 40960, 2 stages
__device__ __forceinline__ void gemm_issue(uint32_t stage_base,
    const __half* Ah, const __half* Al, const __half* Bh,
    int m0, int n0, int ko, int tid)
{
    #pragma unroll
    for (int i = 0; i < 4; i++) {
        int idx = tid + i * 256;          // 0..1023
        int r = idx >> 3, ch = idx & 7;
        uint32_t off = r * 128 + ((ch ^ (r & 7)) << 4);
        cpa16(stage_base + off,         Ah + (size_t)(m0 + r) * E_DIM + ko + ch * 8);
        cpa16(stage_base + 16384 + off, Al + (size_t)(m0 + r) * E_DIM + ko + ch * 8);
    }
    #pragma unroll
    for (int i = 0; i < 2; i++) {
        int idx = tid + i * 256;          // 0..511
        int r = idx >> 3, ch = idx & 7;
        uint32_t off = r * 128 + ((ch ^ (r & 7)) << 4);
        cpa16(stage_base + 32768 + off, Bh + (size_t)(n0 + r) * E_DIM + ko + ch * 8);
    }
}

__global__ __launch_bounds__(256) void gemm_mma(const float* __restrict__ bias,
                                                float* __restrict__ C, int mode)
{
    extern __shared__ char smem[];
    const __half *Ah, *Al, *Bh;
    if (mode == 0) { Ah = g_xh; Al = g_xl; Bh = g_wih; }
    else           { Ah = g_ch; Al = g_cl; Bh = g_woh; }

    const uint32_t sb = smem_u32(smem);
    const int tid = threadIdx.x, lane = tid & 31, wid = tid >> 5;
    const int wm0 = (wid & 3) * 32, wn0 = (wid >> 2) * 32;
    const int m0 = blockIdx.y * 128, n0 = blockIdx.x * 64;

    gemm_issue(sb,         Ah, Al, Bh, m0, n0, 0,  tid); CP_COMMIT();
    gemm_issue(sb + 40960, Ah, Al, Bh, m0, n0, 64, tid); CP_COMMIT();

    float c[2][4][4] = {};
    for (int s = 0; s < 8; s++) {
        CP_WAIT1();
        __syncthreads();
        uint32_t st = sb + (s & 1) * 40960;
        #pragma unroll
        for (int kc = 0; kc < 8; kc += 2) {
            uint32_t ah[2][4], al[2][4], bhf[4][2];
            #pragma unroll
            for (int i = 0; i < 2; i++) {
                ldsm4(addrA(st,         wm0 + i * 16, kc, lane), ah[i]);
                ldsm4(addrA(st + 16384, wm0 + i * 16, kc, lane), al[i]);
            }
            #pragma unroll
            for (int jj = 0; jj < 2; jj++) {
                uint32_t t[4];
                ldsm4(addrB(st + 32768, wn0 + jj * 16, kc, lane), t);
                bhf[jj*2][0] = t[0]; bhf[jj*2][1] = t[1];
                bhf[jj*2+1][0] = t[2]; bhf[jj*2+1][1] = t[3];
            }
            #pragma unroll
            for (int i = 0; i < 2; i++)
                #pragma unroll
                for (int j = 0; j < 4; j++) {
                    mma_h(c[i][j], ah[i], bhf[j]);
                    mma_h(c[i][j], al[i], bhf[j]);
                }
        }
        __syncthreads();
        if (s + 2 < 8)
            gemm_issue(sb + (s & 1) * 40960, Ah, Al, Bh, m0, n0, (s + 2) * 64, tid);
        CP_COMMIT();
    }

    #pragma unroll
    for (int i = 0; i < 2; i++)
        #pragma unroll
        for (int j = 0; j < 4; j++)
            #pragma unroll
            for (int e = 0; e < 4; e++) {
                int rg = m0 + wm0 + i * 16 + (lane >> 2) + ((e >> 1) << 3);
                int n  = n0 + wn0 + j * 8 + (lane & 3) * 2 + (e & 1);
                float v = c[i][j][e] + bias[n];
                if (mode == 0) {
                    int t = rg >> 2, bb = rg & 3;
                    int sect = n >> 9, jm = n & 511;
                    int hh = jm >> 6, d = jm & 63;
                    int bh = bb * 8 + hh;
                    if (sect == 2) {
                        g_vth[((size_t)bh * HD + d) * T_DIM + t] = __float2half_rn(v);
                    } else {
                        size_t dst = ((size_t)bh * T_DIM + t) * HD + d;
                        if (sect == 0) {
                            v *= SCALE;
                            __half h = __float2half_rn(v);
                            g_qh[dst] = h;
                            g_ql[dst] = __float2half_rn(v - __half2float(h));
                        } else {
                            g_kh[dst] = __float2half_rn(v);
                        }
                    }
                } else {
                    C[(size_t)rg * E_DIM + n] = v;
                }
            }
}

// ---------------- flash attention: R6 schedule, fp16 2-pass, hi-only K/V ---------
// 128 threads (4 warps), q-tile 128 (32 rows/warp, full k width per warp).
// smem: QH 0 (16KB), QL 16384, KVbuf0 32768 (K +0, V +8192), KVbuf1 49152 -> 64KB
__device__ __forceinline__ void flash_issue_kv(uint32_t buf, int bh, int k0, int tid)
{
    #pragma unroll
    for (int i = 0; i < 4; i++) {
        int idx = tid + i * 128;          // 0..511
        int r = idx >> 3, ch = idx & 7;
        uint32_t off = r * 128 + ((ch ^ (r & 7)) << 4);
        cpa16(buf + off,        g_kh  + ((size_t)bh * T_DIM + k0 + r) * HD + ch * 8);
        cpa16(buf + 8192 + off, g_vth + ((size_t)bh * HD + r) * T_DIM + k0 + ch * 8);
    }
}

__global__ __launch_bounds__(128, 2) void flash_mma()
{
    extern __shared__ char smem[];
    const uint32_t sb = smem_u32(smem);
    const int tid = threadIdx.x, lane = tid & 31, w = tid >> 5;
    const int bh = blockIdx.y, q0 = blockIdx.x * 128;
    const int b = bh >> 3, h = bh & 7;
    const int wq0 = w * 32;

    flash_issue_kv(sb + 32768, bh, 0, tid);  CP_COMMIT();
    flash_issue_kv(sb + 49152, bh, 64, tid); CP_COMMIT();

    // load Q hi/lo to smem
    {
        const __half* Qh = g_qh + ((size_t)bh * T_DIM + q0) * HD;
        const __half* Ql = g_ql + ((size_t)bh * T_DIM + q0) * HD;
        #pragma unroll
        for (int i = 0; i < 8; i++) {
            int idx = tid + i * 128;      // 0..1023
            int r = idx >> 3, ch = idx & 7;
            uint32_t off = r * 128 + ((ch ^ (r & 7)) << 4);
            *(uint4*)(smem + off)         = *(const uint4*)(Qh + (size_t)r * HD + ch * 8);
            *(uint4*)(smem + 16384 + off) = *(const uint4*)(Ql + (size_t)r * HD + ch * 8);
        }
    }
    __syncthreads();

    // cache Q fragments in registers
    uint32_t qh[2][4][4], ql[2][4][4];
    #pragma unroll
    for (int i = 0; i < 2; i++)
        #pragma unroll
        for (int kk = 0; kk < 4; kk++) {
            ldsm4(addrA(sb,         wq0 + i * 16, 2 * kk, lane), qh[i][kk]);
            ldsm4(addrA(sb + 16384, wq0 + i * 16, 2 * kk, lane), ql[i][kk]);
        }

    float o[2][8][4] = {};
    float rs[4] = {};

    for (int kt = 0; kt < T_DIM / 64; kt++) {
        CP_WAIT1();
        __syncthreads();
        const uint32_t buf = sb + 32768 + (kt & 1) * 16384;

        // S = Q K^T  (32 x 64 per warp, 2-pass)
        float s[2][8][4] = {};
        #pragma unroll
        for (int kk = 0; kk < 4; kk++)
            #pragma unroll
            for (int jj = 0; jj < 4; jj++) {
                uint32_t th[4];
                ldsm4(addrB(buf, jj * 16, 2 * kk, lane), th);
                uint32_t bh0[2] = {th[0], th[1]}, bh1[2] = {th[2], th[3]};
                #pragma unroll
                for (int i = 0; i < 2; i++) {
                    mma_h(s[i][jj*2], qh[i][kk], bh0);
                    mma_h(s[i][jj*2], ql[i][kk], bh0);
                    mma_h(s[i][jj*2+1], qh[i][kk], bh1);
                    mma_h(s[i][jj*2+1], ql[i][kk], bh1);
                }
            }

        // exp (MUFU) + row sums + pack P hi/lo + stream hi to gmem
        uint32_t aPh[2][4][4], aPl[2][4][4];
        #pragma unroll
        for (int i = 0; i < 2; i++)
            #pragma unroll
            for (int j = 0; j < 8; j++) {
                float p0 = __expf(s[i][j][0]), p1 = __expf(s[i][j][1]);
                float p2 = __expf(s[i][j][2]), p3 = __expf(s[i][j][3]);
                rs[i*2]   += p0 + p1;
                rs[i*2+1] += p2 + p3;
                uint32_t lo01, lo23;
                uint32_t hi01 = packsplit_h(p0, p1, &lo01);
                uint32_t hi23 = packsplit_h(p2, p3, &lo23);
                int col = kt * 64 + j * 8 + (lane & 3) * 2;
                int r0 = q0 + wq0 + i * 16 + (lane >> 2);
                __stcs((__half2*)(g_p + ((size_t)bh * T_DIM + r0) * T_DIM + col),
                       *(__half2*)&hi01);
                __stcs((__half2*)(g_p + ((size_t)bh * T_DIM + r0 + 8) * T_DIM + col),
                       *(__half2*)&hi23);
                int kk = j >> 1, m = (j & 1) * 2;
                aPh[i][kk][m]   = hi01; aPh[i][kk][m+1] = hi23;
                aPl[i][kk][m]   = lo01; aPl[i][kk][m+1] = lo23;
            }

        // O += P V  (B = Vt hi in smem, 2-pass on P)
        #pragma unroll
        for (int kk = 0; kk < 4; kk++)
            #pragma unroll
            for (int jj = 0; jj < 4; jj++) {
                uint32_t th[4];
                ldsm4(addrB(buf + 8192, jj * 16, 2 * kk, lane), th);
                uint32_t bh0[2] = {th[0], th[1]}, bh1[2] = {th[2], th[3]};
                #pragma unroll
                for (int i = 0; i < 2; i++) {
                    mma_h(o[i][jj*2], aPh[i][kk], bh0);
                    mma_h(o[i][jj*2], aPl[i][kk], bh0);
                    mma_h(o[i][jj*2+1], aPh[i][kk], bh1);
                    mma_h(o[i][jj*2+1], aPl[i][kk], bh1);
                }
            }
        __syncthreads();
        if (kt + 2 < T_DIM / 64)
            flash_issue_kv(sb + 32768 + (kt & 1) * 16384, bh, (kt + 2) * 64, tid);
        CP_COMMIT();
    }

    // quad-reduce row sums
    #pragma unroll
    for (int x = 0; x < 4; x++) {
        rs[x] += __shfl_xor_sync(0xffffffffu, rs[x], 1);
        rs[x] += __shfl_xor_sync(0xffffffffu, rs[x], 2);
    }
    float il[4] = {1.0f / rs[0], 1.0f / rs[1], 1.0f / rs[2], 1.0f / rs[3]};

    // write ctx (fp16 hi/lo) and 1/l
    #pragma unroll
    for (int i = 0; i < 2; i++)
        #pragma unroll
        for (int hf = 0; hf < 2; hf++) {
            int r = wq0 + i * 16 + (lane >> 2) + hf * 8;
            float s_il = il[i*2 + hf];
            #pragma unroll
            for (int j = 0; j < 8; j++) {
                int cc = j * 8 + (lane & 3) * 2;
                uint32_t lo;
                uint32_t hi = packsplit_h(o[i][j][hf*2] * s_il, o[i][j][hf*2+1] * s_il, &lo);
                size_t off = ((size_t)(q0 + r) * B_DIM + b) * E_DIM + h * HD + cc;
                *(uint32_t*)&g_ch[off] = hi;
                *(uint32_t*)&g_cl[off] = lo;
            }
            if ((lane & 3) == 0)
                g_il[(size_t)bh * T_DIM + q0 + r] = s_il;
        }
}

// ---------------- avg_weights: pure memory pass over stored P ----------------
__global__ __launch_bounds__(256) void avg_sum(float* __restrict__ outAvg)
{
    const int blk = blockIdx.x;
    const int b = blk >> 11, q = blk & 2047;
    const int tid = threadIdx.x;

    float acc[8] = {};
    #pragma unroll
    for (int hh = 0; hh < H_DIM; hh++) {
        const int bh = b * 8 + hh;
        float il = g_il[(size_t)bh * T_DIM + q] * 0.125f;
        uint4 u = *((const uint4*)(g_p + ((size_t)bh * T_DIM + q) * T_DIM) + tid);
        __half2* hp = (__half2*)&u;
        #pragma unroll
        for (int c = 0; c < 4; c++) {
            float2 f = __half22float2(hp[c]);
            acc[c*2]   = fmaf(f.x, il, acc[c*2]);
            acc[c*2+1] = fmaf(f.y, il, acc[c*2+1]);
        }
    }
    float* dst = outAvg + ((size_t)b * T_DIM + q) * T_DIM + tid * 8;
    *(float4*)dst       = make_float4(acc[0], acc[1], acc[2], acc[3]);
    *(float4*)(dst + 4) = make_float4(acc[4], acc[5], acc[6], acc[7]);
}

// ---------------- launch ----------------
extern "C" void kernel_launch(void* const* d_in, const int* in_sizes, int n_in,
                              void* d_out, int out_size)
{
    const float* x     = (const float*)d_in[0];
    const float* w_in  = (const float*)d_in[1];
    const float* b_in  = (const float*)d_in[2];
    const float* w_out = (const float*)d_in[3];
    const float* b_out = (const float*)d_in[4];
    float* out = (float*)d_out;

    static cudaStream_t s2 = nullptr;
    static cudaEvent_t ev1 = nullptr, ev2 = nullptr;
    if (!s2) {
        cudaStreamCreateWithFlags(&s2, cudaStreamNonBlocking);
        cudaEventCreateWithFlags(&ev1, cudaEventDisableTiming);
        cudaEventCreateWithFlags(&ev2, cudaEventDisableTiming);
    }

    split_all<<<(NX + NWI + NWO + 255) / 256, 256>>>(x, w_in, w_out);

    cudaFuncSetAttribute(gemm_mma, cudaFuncAttributeMaxDynamicSharedMemorySize, 81920);
    gemm_mma<<<dim3(3 * E_DIM / 64, M_ROWS / 128), 256, 81920>>>(b_in, out, 0);

    cudaFuncSetAttribute(flash_mma, cudaFuncAttributeMaxDynamicSharedMemorySize, 65536);
    flash_mma<<<dim3(T_DIM / 128, BH), 128, 65536>>>();

    // fork: avg_sum (DRAM-bound) runs concurrently with out-proj gemm (tensor-bound)
    cudaEventRecord(ev1, 0);
    cudaStreamWaitEvent(s2, ev1, 0);
    avg_sum<<<B_DIM * T_DIM, 256, 0, s2>>>(out + ATTN_ELEMS);
    cudaEventRecord(ev2, s2);

    gemm_mma<<<dim3(E_DIM / 64, M_ROWS / 128), 256, 81920>>>(b_out, out, 1);

    cudaStreamWaitEvent(0, ev2, 0);
}